// round 5
// baseline (speedup 1.0000x reference)
#include <cuda_runtime.h>
#include <cuda_bf16.h>
#include <cstdint>
#include <math.h>

// ---------------------------------------------------------------------------
// Problem constants
// ---------------------------------------------------------------------------
#define B_   4
#define V_   6
#define C_   256
#define C2_  128          // C/2 packed bf16 pairs
#define HW_  4096
#define NH_  8
#define DH_  32
#define CHW_ (C_ * HW_)

// GEMM tiling
#define MT   128
#define NTT  128
#define KB   32           // k chunk (16 pairs)
#define NKCH (C_ / KB)    // 8

// smem: A and B both [row][k2] u32, pitch 20 (16 data + 4 pad)
#define AP    20
#define M_U   (128 * AP)                  // 2560 u32 per matrix
#define BUF_U (4 * M_U)                   // Ah, Al, Bh, Bl = 10240
#define SMEM_MMA (2 * BUF_U * 4)          // 81920 B

// ---------------------------------------------------------------------------
// Scratch (device globals)
// ---------------------------------------------------------------------------
__device__ __align__(128) uint32_t g_xpk_hi [B_ * V_ * HW_ * C2_];  // [(b v)][p][c2]
__device__ __align__(128) uint32_t g_xpk_lo [B_ * V_ * HW_ * C2_];
__device__ __align__(128) uint32_t g_xmpk_hi[B_ * HW_ * C2_];       // [b][p][c2]
__device__ __align__(128) uint32_t g_xmpk_lo[B_ * HW_ * C2_];
__device__ __align__(128) uint32_t g_wpk_hi [4 * C_ * C2_];         // [w][o][c2]
__device__ __align__(128) uint32_t g_wpk_lo [4 * C_ * C2_];
__device__ __align__(128) uint32_t g_apk_hi [B_ * HW_ * C2_];       // [b][p][c2]
__device__ __align__(128) uint32_t g_apk_lo [B_ * HW_ * C2_];
__device__ __align__(128) float g_qloc[B_ * CHW_];
__device__ __align__(128) float g_kbuf[B_ * V_ * CHW_];
__device__ __align__(128) float g_vbuf[B_ * V_ * CHW_];

// ---------------------------------------------------------------------------
// Helpers
// ---------------------------------------------------------------------------
__device__ __forceinline__ uint32_t smem_u32(const void* p) {
    uint32_t a;
    asm("{ .reg .u64 t; cvta.to.shared.u64 t, %1; cvt.u32.u64 %0, t; }" : "=r"(a) : "l"(p));
    return a;
}
__device__ __forceinline__ uint32_t packbf(float e0, float e1) {
    return ((uint32_t)__bfloat16_as_ushort(__float2bfloat16_rn(e1)) << 16)
         | (uint32_t)__bfloat16_as_ushort(__float2bfloat16_rn(e0));
}
__device__ __forceinline__ float bfres(float v) {
    return v - __bfloat162float(__float2bfloat16_rn(v));
}
__device__ __forceinline__ void mma16816(float* c, const uint32_t* a,
                                         uint32_t b0, uint32_t b1) {
    asm volatile(
        "mma.sync.aligned.m16n8k16.row.col.f32.bf16.bf16.f32 "
        "{%0,%1,%2,%3}, {%4,%5,%6,%7}, {%8,%9}, {%0,%1,%2,%3};\n"
        : "+f"(c[0]), "+f"(c[1]), "+f"(c[2]), "+f"(c[3])
        : "r"(a[0]), "r"(a[1]), "r"(a[2]), "r"(a[3]), "r"(b0), "r"(b1));
}
__device__ __forceinline__ void ldsm4(uint32_t* r, uint32_t addr) {
    asm volatile("ldmatrix.sync.aligned.m8n8.x4.shared.b16 {%0,%1,%2,%3}, [%4];"
                 : "=r"(r[0]), "=r"(r[1]), "=r"(r[2]), "=r"(r[3]) : "r"(addr));
}
__device__ __forceinline__ void cpasync16(uint32_t dst, const void* src) {
    asm volatile("cp.async.cg.shared.global [%0], [%1], 16;\n" :: "r"(dst), "l"(src));
}
#define CP_COMMIT() asm volatile("cp.async.commit_group;\n" ::: "memory")
#define CP_WAIT(n)  asm volatile("cp.async.wait_group %0;\n" :: "n"(n) : "memory")

// ---------------------------------------------------------------------------
// prep_w: split + pair-pack the four 256x256 weights. [w][o][c2]
// ---------------------------------------------------------------------------
__global__ void __launch_bounds__(256) prep_w_kernel(
    const float* __restrict__ Wq, const float* __restrict__ Wk,
    const float* __restrict__ Wv, const float* __restrict__ Wo,
    uint32_t* __restrict__ hi, uint32_t* __restrict__ lo)
{
    const int i = blockIdx.x * 256 + threadIdx.x;
    const int w = i >> 15;
    const int r = i & 32767;
    const float* src = (w == 0) ? Wq : (w == 1) ? Wk : (w == 2) ? Wv : Wo;
    const float2 f = *(const float2*)(src + r * 2);
    hi[i] = packbf(f.x, f.y);
    lo[i] = packbf(bfres(f.x), bfres(f.y));
}

// ---------------------------------------------------------------------------
// prep_x: fused view-mean + split + pack + TRANSPOSE to [p][c2].
// grid (C/32, HW/32, B), block (32, 8)
// ---------------------------------------------------------------------------
__global__ void __launch_bounds__(256) prep_x_kernel(
    const float* __restrict__ x,
    uint32_t* __restrict__ xhi, uint32_t* __restrict__ xlo,
    uint32_t* __restrict__ mhi, uint32_t* __restrict__ mlo)
{
    __shared__ float t[32][33];
    const int c0 = blockIdx.x * 32, p0 = blockIdx.y * 32, b = blockIdx.z;
    const int tx = threadIdx.x, ty = threadIdx.y;
    const int tid = ty * 32 + tx;
    const int c2i = tid & 15;          // writer: c2 within tile
    const int pr0 = tid >> 4;          // writer: p row (and +16)

    float acc[4] = {0.f, 0.f, 0.f, 0.f};
    for (int v = 0; v < V_; ++v) {
#pragma unroll
        for (int i = 0; i < 4; ++i) {
            const float val = x[((size_t)((b * V_ + v) * C_) + c0 + ty + i * 8) * HW_ + p0 + tx];
            t[ty + i * 8][tx] = val;
            acc[i] += val;
        }
        __syncthreads();
#pragma unroll
        for (int r = 0; r < 2; ++r) {
            const int pr = pr0 + r * 16;
            const float e0 = t[2 * c2i][pr], e1 = t[2 * c2i + 1][pr];
            const size_t o = ((size_t)(b * V_ + v) * HW_ + p0 + pr) * C2_ + (c0 >> 1) + c2i;
            xhi[o] = packbf(e0, e1);
            xlo[o] = packbf(bfres(e0), bfres(e1));
        }
        __syncthreads();
    }
#pragma unroll
    for (int i = 0; i < 4; ++i) t[ty + i * 8][tx] = acc[i] * (1.0f / 6.0f);
    __syncthreads();
#pragma unroll
    for (int r = 0; r < 2; ++r) {
        const int pr = pr0 + r * 16;
        const float e0 = t[2 * c2i][pr], e1 = t[2 * c2i + 1][pr];
        const size_t o = ((size_t)b * HW_ + p0 + pr) * C2_ + (c0 >> 1) + c2i;
        mhi[o] = packbf(e0, e1);
        mlo[o] = packbf(bfres(e0), bfres(e1));
    }
}

// ---------------------------------------------------------------------------
// HMMA GEMM, ldmatrix edition.  Y[z][o][p] = sum_c W[o][c] * X[z][p][c]^T
//   W packed [o][c2], X packed [p][c2]; both K-major. 3-product bf16 split.
// ---------------------------------------------------------------------------
template <int KV>
__global__ void __launch_bounds__(256) gemm_pk(
    const uint32_t* __restrict__ Wh0, const uint32_t* __restrict__ Wl0,
    const uint32_t* __restrict__ Wh1, const uint32_t* __restrict__ Wl1,
    const uint32_t* __restrict__ Xh,  const uint32_t* __restrict__ Xl,
    float* __restrict__ Y0g, float* __restrict__ Y1g)
{
    extern __shared__ __align__(16) uint32_t smem[];
    const uint32_t sb = smem_u32(smem);

    const uint32_t *Wh, *Wl, *Xhz, *Xlz;
    float* Y;
    if (KV) {
        const int view = blockIdx.z >> 1;
        const int sel = blockIdx.z & 1;
        Wh = sel ? Wh1 : Wh0;
        Wl = sel ? Wl1 : Wl0;
        const size_t xoff = (size_t)view * HW_ * C2_;
        Xhz = Xh + xoff; Xlz = Xl + xoff;
        Y = (sel ? Y1g : Y0g) + (size_t)view * CHW_;
    } else {
        Wh = Wh0; Wl = Wl0;
        const size_t xoff = (size_t)blockIdx.z * HW_ * C2_;
        Xhz = Xh + xoff; Xlz = Xl + xoff;
        Y = Y0g + (size_t)blockIdx.z * CHW_;
    }

    const int tid = threadIdx.x;
    const int lane = tid & 31;
    const int wid = tid >> 5;
    const int p0 = blockIdx.x * NTT;
    const int o0 = blockIdx.y * MT;

    // cp.async mapping: per matrix, thread covers row tid>>1, 8 u32 at (tid&1)*8
    const int cp_row = tid >> 1;
    const int cp_col = (tid & 1) * 8;

    // mma fragment indices
    const int g = lane >> 2;
    const int t = lane & 3;
    const int mwb = (wid & 3) * 32;
    const int nwb = (wid >> 2) * 64;

    // ldmatrix lane address components (u32 units within a matrix)
    const int a_off = (lane & 15) * AP + (lane >> 4) * 4;            // + m-tile*16*AP + s*8
    const int b_off = ((lane & 7) + ((lane >> 4) & 1) * 8) * AP + ((lane >> 3) & 1) * 4;

    float acc[2][8][4];
#pragma unroll
    for (int mi = 0; mi < 2; ++mi)
#pragma unroll
        for (int ni = 0; ni < 8; ++ni)
#pragma unroll
            for (int j = 0; j < 4; ++j) acc[mi][ni][j] = 0.f;

    auto issue = [&](int kc, int buf) {
        const uint32_t base = sb + buf * BUF_U * 4;
        const size_t wsrc = (size_t)(o0 + cp_row) * C2_ + kc * 16 + cp_col;
        const size_t xsrc = (size_t)(p0 + cp_row) * C2_ + kc * 16 + cp_col;
        const uint32_t dst = (cp_row * AP + cp_col) * 4;
#pragma unroll
        for (int h = 0; h < 2; ++h) {
            cpasync16(base + 0 * M_U * 4 + dst + h * 16, Wh + wsrc + h * 4);
            cpasync16(base + 1 * M_U * 4 + dst + h * 16, Wl + wsrc + h * 4);
            cpasync16(base + 2 * M_U * 4 + dst + h * 16, Xhz + xsrc + h * 4);
            cpasync16(base + 3 * M_U * 4 + dst + h * 16, Xlz + xsrc + h * 4);
        }
        CP_COMMIT();
    };

    issue(0, 0);

    for (int kc = 0; kc < NKCH; ++kc) {
        if (kc + 1 < NKCH) {
            issue(kc + 1, (kc + 1) & 1);
            CP_WAIT(1);
        } else {
            CP_WAIT(0);
        }
        __syncthreads();

        const uint32_t bb = sb + (kc & 1) * BUF_U * 4;
        const uint32_t sAh = bb;
        const uint32_t sAl = bb + M_U * 4;
        const uint32_t sBh = bb + 2 * M_U * 4;
        const uint32_t sBl = bb + 3 * M_U * 4;

#pragma unroll
        for (int s = 0; s < 2; ++s) {
            const uint32_t soff = s * 32;             // 8 u32
            uint32_t ah[2][4], al[2][4];
#pragma unroll
            for (int mi = 0; mi < 2; ++mi) {
                const uint32_t ao = ((mwb + mi * 16) * AP + a_off) * 4 + soff;
                ldsm4(ah[mi], sAh + ao);
                ldsm4(al[mi], sAl + ao);
            }
#pragma unroll
            for (int np = 0; np < 4; ++np) {
                const uint32_t bo = ((nwb + np * 16) * AP + b_off) * 4 + soff;
                uint32_t bh[4], bl[4];
                ldsm4(bh, sBh + bo);
                ldsm4(bl, sBl + bo);
#pragma unroll
                for (int tl = 0; tl < 2; ++tl) {
#pragma unroll
                    for (int mi = 0; mi < 2; ++mi) {
                        float* a = acc[mi][np * 2 + tl];
                        mma16816(a, ah[mi], bh[tl * 2], bh[tl * 2 + 1]);
                        mma16816(a, ah[mi], bl[tl * 2], bl[tl * 2 + 1]);
                        mma16816(a, al[mi], bh[tl * 2], bh[tl * 2 + 1]);
                    }
                }
            }
        }
        __syncthreads();
    }

    // epilogue: fp32 [o][p]
#pragma unroll
    for (int mi = 0; mi < 2; ++mi) {
        const int o = o0 + mwb + mi * 16 + g;
#pragma unroll
        for (int ni = 0; ni < 8; ++ni) {
            const int p = p0 + nwb + ni * 8 + t * 2;
            *(float2*)(Y + (size_t)o * HW_ + p) =
                make_float2(acc[mi][ni][0], acc[mi][ni][1]);
            *(float2*)(Y + (size_t)(o + 8) * HW_ + p) =
                make_float2(acc[mi][ni][2], acc[mi][ni][3]);
        }
    }
}

// ---------------------------------------------------------------------------
// Per-pixel cross-view attention; emits packed bf16 hi/lo in [b][p][c2],
// transposed through smem for coalesced stores.
// ---------------------------------------------------------------------------
__global__ void __launch_bounds__(256) attn_kernel(
    const float* __restrict__ Q, const float* __restrict__ K,
    const float* __restrict__ Vv,
    uint32_t* __restrict__ Ohi, uint32_t* __restrict__ Olo)
{
    __shared__ uint32_t ts[8][32][17];
    const int p = ((blockIdx.x & 15) << 8) + threadIdx.x;
    const int bh = blockIdx.x >> 4;
    const int b = bh >> 3;
    const int h = bh & 7;
    const int w = threadIdx.x >> 5;
    const int l = threadIdx.x & 31;

    const size_t qbase = ((size_t)(b * C_ + h * DH_)) * HW_ + p;

    float q[DH_];
#pragma unroll
    for (int d = 0; d < DH_; ++d) q[d] = Q[qbase + (size_t)d * HW_];

    float s[V_];
#pragma unroll
    for (int v = 0; v < V_; ++v) {
        const size_t kb = ((size_t)((b * V_ + v) * C_ + h * DH_)) * HW_ + p;
        float dot = 0.f;
#pragma unroll
        for (int d = 0; d < DH_; ++d) dot += q[d] * K[kb + (size_t)d * HW_];
        s[v] = dot * 0.17677669529663687f;
    }
    float m = s[0];
#pragma unroll
    for (int v = 1; v < V_; ++v) m = fmaxf(m, s[v]);
    float sum = 0.f;
#pragma unroll
    for (int v = 0; v < V_; ++v) { s[v] = expf(s[v] - m); sum += s[v]; }
    const float invsum = 1.f / sum;

    float acc[DH_];
#pragma unroll
    for (int d = 0; d < DH_; ++d) acc[d] = 0.f;
#pragma unroll
    for (int v = 0; v < V_; ++v) {
        const float wgt = s[v] * invsum;
        const size_t vb = ((size_t)((b * V_ + v) * C_ + h * DH_)) * HW_ + p;
#pragma unroll
        for (int d = 0; d < DH_; ++d) acc[d] += wgt * Vv[vb + (size_t)d * HW_];
    }

    // transpose to [p][c2] via per-warp smem tile
    const int pwbase = ((blockIdx.x & 15) << 8) + w * 32;
    const int c2i = l & 15;
    const size_t obase = ((size_t)b * HW_ + pwbase) * C2_ + h * 16 + c2i;

#pragma unroll
    for (int i = 0; i < 16; ++i) ts[w][l][i] = packbf(acc[2 * i], acc[2 * i + 1]);
    __syncwarp();
#pragma unroll
    for (int r = 0; r < 16; ++r) {
        const int pr = r * 2 + (l >> 4);
        Ohi[obase + (size_t)pr * C2_] = ts[w][pr][c2i];
    }
    __syncwarp();
#pragma unroll
    for (int i = 0; i < 16; ++i)
        ts[w][l][i] = packbf(bfres(acc[2 * i]), bfres(acc[2 * i + 1]));
    __syncwarp();
#pragma unroll
    for (int r = 0; r < 16; ++r) {
        const int pr = r * 2 + (l >> 4);
        Olo[obase + (size_t)pr * C2_] = ts[w][pr][c2i];
    }
}

// ---------------------------------------------------------------------------
// kernel_launch
// ---------------------------------------------------------------------------
extern "C" void kernel_launch(void* const* d_in, const int* in_sizes, int n_in,
                              void* d_out, int out_size)
{
    const float* x  = (const float*)d_in[0];
    const float* Wq = (const float*)d_in[1];
    const float* Wk = (const float*)d_in[2];
    const float* Wv = (const float*)d_in[3];
    const float* Wo = (const float*)d_in[4];
    float* out = (float*)d_out;

    void* p;
    cudaGetSymbolAddress(&p, g_xpk_hi);  uint32_t* xhi = (uint32_t*)p;
    cudaGetSymbolAddress(&p, g_xpk_lo);  uint32_t* xlo = (uint32_t*)p;
    cudaGetSymbolAddress(&p, g_xmpk_hi); uint32_t* mhi = (uint32_t*)p;
    cudaGetSymbolAddress(&p, g_xmpk_lo); uint32_t* mlo = (uint32_t*)p;
    cudaGetSymbolAddress(&p, g_wpk_hi);  uint32_t* whi = (uint32_t*)p;
    cudaGetSymbolAddress(&p, g_wpk_lo);  uint32_t* wlo = (uint32_t*)p;
    cudaGetSymbolAddress(&p, g_apk_hi);  uint32_t* ahi = (uint32_t*)p;
    cudaGetSymbolAddress(&p, g_apk_lo);  uint32_t* alo = (uint32_t*)p;
    cudaGetSymbolAddress(&p, g_qloc);    float* qloc = (float*)p;
    cudaGetSymbolAddress(&p, g_kbuf);    float* kbuf = (float*)p;
    cudaGetSymbolAddress(&p, g_vbuf);    float* vbuf = (float*)p;

    cudaFuncSetAttribute(gemm_pk<0>, cudaFuncAttributeMaxDynamicSharedMemorySize, SMEM_MMA);
    cudaFuncSetAttribute(gemm_pk<1>, cudaFuncAttributeMaxDynamicSharedMemorySize, SMEM_MMA);

    const int WSZ = C_ * C2_;

    prep_w_kernel<<<4 * WSZ / 256, 256>>>(Wq, Wk, Wv, Wo, whi, wlo);
    {
        dim3 g(C_ / 32, HW_ / 32, B_);
        prep_x_kernel<<<g, dim3(32, 8)>>>(x, xhi, xlo, mhi, mlo);
    }
    {
        dim3 g(HW_ / NTT, C_ / MT, B_);
        gemm_pk<0><<<g, 256, SMEM_MMA>>>(whi + 0 * WSZ, wlo + 0 * WSZ,
                                         nullptr, nullptr, mhi, mlo, qloc, nullptr);
    }
    {
        dim3 g(HW_ / NTT, C_ / MT, B_ * V_ * 2);
        gemm_pk<1><<<g, 256, SMEM_MMA>>>(whi + 1 * WSZ, wlo + 1 * WSZ,
                                         whi + 2 * WSZ, wlo + 2 * WSZ,
                                         xhi, xlo, kbuf, vbuf);
    }
    attn_kernel<<<B_ * NH_ * (HW_ / 256), 256>>>(qloc, kbuf, vbuf, ahi, alo);
    {
        dim3 g(HW_ / NTT, C_ / MT, B_);
        gemm_pk<0><<<g, 256, SMEM_MMA>>>(whi + 3 * WSZ, wlo + 3 * WSZ,
                                         nullptr, nullptr, ahi, alo, out, nullptr);
    }
}

// round 6
// speedup vs baseline: 1.3187x; 1.3187x over previous
#include <cuda_runtime.h>
#include <cuda_fp16.h>
#include <cstdint>
#include <math.h>

// ---------------------------------------------------------------------------
// Problem constants
// ---------------------------------------------------------------------------
#define B_   4
#define V_   6
#define C_   256
#define C2_  128          // C/2 packed fp16 pairs
#define HW_  4096
#define NH_  8
#define DH_  32
#define CHW_ (C_ * HW_)

// GEMM tiling
#define MT   128
#define NTT  128
#define KB   32           // k chunk (16 pairs)
#define NKCH (C_ / KB)    // 8

// smem (u32 units): A [m][k2] pitch 20; B [k2][p] pitch 136
#define AP    20
#define A_U   (MT * AP)                   // 2560
#define BPAD  136
#define B_U   (16 * BPAD)                 // 2176
#define BUF_U (2 * A_U + B_U)             // Ah, Al, Bh = 7296
#define NSTG  3
#define SMEM_MMA (NSTG * BUF_U * 4)       // 87552 B

// ---------------------------------------------------------------------------
// Scratch (device globals)
// ---------------------------------------------------------------------------
__device__ __align__(128) uint32_t g_xpk_hi [B_ * V_ * C2_ * HW_];  // [(b v)][c2][p]
__device__ __align__(128) uint32_t g_xmpk_hi[B_ * C2_ * HW_];       // [b][c2][p]
__device__ __align__(128) uint32_t g_wpk_hi [4 * C_ * C2_];         // [w][o][c2]
__device__ __align__(128) uint32_t g_wpk_lo [4 * C_ * C2_];
__device__ __align__(128) uint32_t g_apk_hi [B_ * C2_ * HW_];       // attn out
__device__ __align__(128) float g_qloc[B_ * CHW_];
__device__ __align__(128) float g_kbuf[B_ * V_ * CHW_];
__device__ __align__(128) float g_vbuf[B_ * V_ * CHW_];

// ---------------------------------------------------------------------------
// Helpers
// ---------------------------------------------------------------------------
__device__ __forceinline__ uint32_t smem_u32(const void* p) {
    uint32_t a;
    asm("{ .reg .u64 t; cvta.to.shared.u64 t, %1; cvt.u32.u64 %0, t; }" : "=r"(a) : "l"(p));
    return a;
}
__device__ __forceinline__ uint32_t packhf(float e0, float e1) {
    // low 16 = e0 (even k), high 16 = e1 (odd k)
    return ((uint32_t)__half_as_ushort(__float2half_rn(e1)) << 16)
         | (uint32_t)__half_as_ushort(__float2half_rn(e0));
}
__device__ __forceinline__ float hfres(float v) {
    return v - __half2float(__float2half_rn(v));
}
__device__ __forceinline__ void mma16816(float* c, const uint32_t* a,
                                         uint32_t b0, uint32_t b1) {
    asm volatile(
        "mma.sync.aligned.m16n8k16.row.col.f32.f16.f16.f32 "
        "{%0,%1,%2,%3}, {%4,%5,%6,%7}, {%8,%9}, {%0,%1,%2,%3};\n"
        : "+f"(c[0]), "+f"(c[1]), "+f"(c[2]), "+f"(c[3])
        : "r"(a[0]), "r"(a[1]), "r"(a[2]), "r"(a[3]), "r"(b0), "r"(b1));
}
__device__ __forceinline__ void cpasync16(uint32_t dst, const void* src) {
    asm volatile("cp.async.cg.shared.global [%0], [%1], 16;\n" :: "r"(dst), "l"(src));
}
#define CP_COMMIT() asm volatile("cp.async.commit_group;\n" ::: "memory")
#define CP_WAIT(n)  asm volatile("cp.async.wait_group %0;\n" :: "n"(n) : "memory")

// ---------------------------------------------------------------------------
// prep_w: split + pair-pack the four 256x256 weights (fp16 hi/lo). [w][o][c2]
// ---------------------------------------------------------------------------
__global__ void __launch_bounds__(256) prep_w_kernel(
    const float* __restrict__ Wq, const float* __restrict__ Wk,
    const float* __restrict__ Wv, const float* __restrict__ Wo,
    uint32_t* __restrict__ hi, uint32_t* __restrict__ lo)
{
    const int i = blockIdx.x * 256 + threadIdx.x;
    const int w = i >> 15;
    const int r = i & 32767;
    const float* src = (w == 0) ? Wq : (w == 1) ? Wk : (w == 2) ? Wv : Wo;
    const float2 f = *(const float2*)(src + r * 2);
    hi[i] = packhf(f.x, f.y);
    lo[i] = packhf(hfres(f.x), hfres(f.y));
}

// ---------------------------------------------------------------------------
// prep_x: fused view-mean + fp16 pair-pack (hi only).
//   x[b][v][c][p] fp32 -> xpk[(b v)][c2][p], xmpk[b][c2][p]
// grid (HW/1024, C2, B), block 256; thread handles 4 p's.
// ---------------------------------------------------------------------------
__global__ void __launch_bounds__(256) prep_x_kernel(
    const float* __restrict__ x,
    uint32_t* __restrict__ xhi, uint32_t* __restrict__ mhi)
{
    const int p  = blockIdx.x * 1024 + threadIdx.x * 4;
    const int c2 = blockIdx.y;
    const int b  = blockIdx.z;

    float4 se = make_float4(0.f, 0.f, 0.f, 0.f);
    float4 so = make_float4(0.f, 0.f, 0.f, 0.f);
#pragma unroll
    for (int v = 0; v < V_; ++v) {
        const float* base = x + ((size_t)((b * V_ + v) * C_) + c2 * 2) * HW_ + p;
        const float4 e = *(const float4*)base;
        const float4 o = *(const float4*)(base + HW_);
        se.x += e.x; se.y += e.y; se.z += e.z; se.w += e.w;
        so.x += o.x; so.y += o.y; so.z += o.z; so.w += o.w;
        const size_t dst = ((size_t)(b * V_ + v) * C2_ + c2) * HW_ + p;
        *(uint4*)(xhi + dst) = make_uint4(packhf(e.x, o.x), packhf(e.y, o.y),
                                          packhf(e.z, o.z), packhf(e.w, o.w));
    }
    const float inv = 1.0f / 6.0f;
    const size_t dst = ((size_t)b * C2_ + c2) * HW_ + p;
    *(uint4*)(mhi + dst) = make_uint4(
        packhf(se.x * inv, so.x * inv), packhf(se.y * inv, so.y * inv),
        packhf(se.z * inv, so.z * inv), packhf(se.w * inv, so.w * inv));
}

// ---------------------------------------------------------------------------
// HMMA GEMM, fp16 2-product:  Y[z][o][p] = sum_c W[o][c] * X[z][c][p]
//   D = Wh*Xh + Wl*Xh (X truncated to fp16), fp32 accumulate.
//   3-stage cp.async pipeline. KV=1: z in [0,48): view=z>>1, sel=z&1.
// ---------------------------------------------------------------------------
template <int KV>
__global__ void __launch_bounds__(256) gemm_pk(
    const uint32_t* __restrict__ Wh0, const uint32_t* __restrict__ Wl0,
    const uint32_t* __restrict__ Wh1, const uint32_t* __restrict__ Wl1,
    const uint32_t* __restrict__ Xh,
    float* __restrict__ Y0g, float* __restrict__ Y1g)
{
    extern __shared__ __align__(16) uint32_t smem[];
    const uint32_t sb = smem_u32(smem);

    const uint32_t *Wh, *Wl, *Xhz;
    float* Y;
    if (KV) {
        const int view = blockIdx.z >> 1;
        const int sel = blockIdx.z & 1;
        Wh = sel ? Wh1 : Wh0;
        Wl = sel ? Wl1 : Wl0;
        Xhz = Xh + (size_t)view * C2_ * HW_;
        Y = (sel ? Y1g : Y0g) + (size_t)view * CHW_;
    } else {
        Wh = Wh0; Wl = Wl0;
        Xhz = Xh + (size_t)blockIdx.z * C2_ * HW_;
        Y = Y0g + (size_t)blockIdx.z * CHW_;
    }

    const int tid = threadIdx.x;
    const int lane = tid & 31;
    const int wid = tid >> 5;
    const int p0 = blockIdx.x * NTT;
    const int o0 = blockIdx.y * MT;

    // async-copy indices
    const int a_o  = tid >> 2;          // 0..63 (+64)
    const int a_k4 = (tid & 3) * 4;
    const int b_r  = tid >> 5;          // 0..7 (+8)
    const int b_p4 = (tid & 31) * 4;

    // mma fragment indices
    const int g = lane >> 2;
    const int t = lane & 3;
    const int mwb = (wid & 3) * 32;
    const int nwb = (wid >> 2) * 64;

    float acc[2][8][4];
#pragma unroll
    for (int mi = 0; mi < 2; ++mi)
#pragma unroll
        for (int ni = 0; ni < 8; ++ni)
#pragma unroll
            for (int j = 0; j < 4; ++j) acc[mi][ni][j] = 0.f;

    auto issue = [&](int kc, int buf) {
        const uint32_t base = sb + buf * BUF_U * 4;
        const uint32_t dAh = base;
        const uint32_t dAl = base + A_U * 4;
        const uint32_t dBh = base + 2 * A_U * 4;
#pragma unroll
        for (int r = 0; r < 2; ++r) {
            const int o = a_o + r * 64;
            const size_t wsrc = (size_t)(o0 + o) * C2_ + kc * 16 + a_k4;
            const uint32_t wdst = (o * AP + a_k4) * 4;
            cpasync16(dAh + wdst, Wh + wsrc);
            cpasync16(dAl + wdst, Wl + wsrc);
            const int row = b_r + r * 8;
            const size_t xsrc = (size_t)(kc * 16 + row) * HW_ + p0 + b_p4;
            cpasync16(dBh + (row * BPAD + b_p4) * 4, Xhz + xsrc);
        }
        CP_COMMIT();
    };

    issue(0, 0);
    issue(1, 1);

    for (int kc = 0; kc < NKCH; ++kc) {
        if (kc == NKCH - 1) CP_WAIT(0); else CP_WAIT(1);
        __syncthreads();
        if (kc + 2 < NKCH) issue(kc + 2, (kc + 2) % NSTG);

        const uint32_t* bb = smem + (kc % NSTG) * BUF_U;
        const uint32_t* sAh = bb;
        const uint32_t* sAl = bb + A_U;
        const uint32_t* sBh = bb + 2 * A_U;

#pragma unroll
        for (int s = 0; s < 2; ++s) {
            const int k2r0 = s * 8 + t;
            const int k2r1 = s * 8 + t + 4;
            uint32_t ah[2][4], al[2][4];
#pragma unroll
            for (int mi = 0; mi < 2; ++mi) {
                const int m0 = mwb + mi * 16 + g;
                ah[mi][0] = sAh[m0 * AP + k2r0];
                ah[mi][1] = sAh[(m0 + 8) * AP + k2r0];
                ah[mi][2] = sAh[m0 * AP + k2r1];
                ah[mi][3] = sAh[(m0 + 8) * AP + k2r1];
                al[mi][0] = sAl[m0 * AP + k2r0];
                al[mi][1] = sAl[(m0 + 8) * AP + k2r0];
                al[mi][2] = sAl[m0 * AP + k2r1];
                al[mi][3] = sAl[(m0 + 8) * AP + k2r1];
            }
#pragma unroll
            for (int ni = 0; ni < 8; ++ni) {
                const int n0 = nwb + ni * 8 + g;
                const uint32_t bh0 = sBh[k2r0 * BPAD + n0];
                const uint32_t bh1 = sBh[k2r1 * BPAD + n0];
#pragma unroll
                for (int mi = 0; mi < 2; ++mi) {
                    mma16816(acc[mi][ni], ah[mi], bh0, bh1);
                    mma16816(acc[mi][ni], al[mi], bh0, bh1);
                }
            }
        }
        __syncthreads();
    }

    // epilogue: fp32 [o][p]
#pragma unroll
    for (int mi = 0; mi < 2; ++mi) {
        const int o = o0 + mwb + mi * 16 + g;
#pragma unroll
        for (int ni = 0; ni < 8; ++ni) {
            const int p = p0 + nwb + ni * 8 + t * 2;
            *(float2*)(Y + (size_t)o * HW_ + p) =
                make_float2(acc[mi][ni][0], acc[mi][ni][1]);
            *(float2*)(Y + (size_t)(o + 8) * HW_ + p) =
                make_float2(acc[mi][ni][2], acc[mi][ni][3]);
        }
    }
}

// ---------------------------------------------------------------------------
// Per-pixel cross-view attention; emits pair-packed fp16 output [b][c2][p].
// ---------------------------------------------------------------------------
__global__ void __launch_bounds__(256) attn_kernel(
    const float* __restrict__ Q, const float* __restrict__ K,
    const float* __restrict__ Vv, uint32_t* __restrict__ Ohi)
{
    const int p = ((blockIdx.x & 15) << 8) + threadIdx.x;
    const int bh = blockIdx.x >> 4;
    const int b = bh >> 3;
    const int h = bh & 7;

    const size_t qbase = ((size_t)(b * C_ + h * DH_)) * HW_ + p;

    float q[DH_];
#pragma unroll
    for (int d = 0; d < DH_; ++d) q[d] = Q[qbase + (size_t)d * HW_];

    float s[V_];
#pragma unroll
    for (int v = 0; v < V_; ++v) {
        const size_t kb = ((size_t)((b * V_ + v) * C_ + h * DH_)) * HW_ + p;
        float dot = 0.f;
#pragma unroll
        for (int d = 0; d < DH_; ++d) dot += q[d] * K[kb + (size_t)d * HW_];
        s[v] = dot * 0.17677669529663687f;
    }
    float m = s[0];
#pragma unroll
    for (int v = 1; v < V_; ++v) m = fmaxf(m, s[v]);
    float sum = 0.f;
#pragma unroll
    for (int v = 0; v < V_; ++v) { s[v] = expf(s[v] - m); sum += s[v]; }
    const float invsum = 1.f / sum;

    float acc[DH_];
#pragma unroll
    for (int d = 0; d < DH_; ++d) acc[d] = 0.f;
#pragma unroll
    for (int v = 0; v < V_; ++v) {
        const float w = s[v] * invsum;
        const size_t vb = ((size_t)((b * V_ + v) * C_ + h * DH_)) * HW_ + p;
#pragma unroll
        for (int d = 0; d < DH_; ++d) acc[d] += w * Vv[vb + (size_t)d * HW_];
    }
    const size_t obase = ((size_t)(b * C2_ + h * (DH_ / 2))) * HW_ + p;
#pragma unroll
    for (int d2 = 0; d2 < DH_ / 2; ++d2)
        Ohi[obase + (size_t)d2 * HW_] = packhf(acc[d2 * 2], acc[d2 * 2 + 1]);
}

// ---------------------------------------------------------------------------
// kernel_launch
// ---------------------------------------------------------------------------
extern "C" void kernel_launch(void* const* d_in, const int* in_sizes, int n_in,
                              void* d_out, int out_size)
{
    const float* x  = (const float*)d_in[0];
    const float* Wq = (const float*)d_in[1];
    const float* Wk = (const float*)d_in[2];
    const float* Wv = (const float*)d_in[3];
    const float* Wo = (const float*)d_in[4];
    float* out = (float*)d_out;

    void* p;
    cudaGetSymbolAddress(&p, g_xpk_hi);  uint32_t* xhi = (uint32_t*)p;
    cudaGetSymbolAddress(&p, g_xmpk_hi); uint32_t* mhi = (uint32_t*)p;
    cudaGetSymbolAddress(&p, g_wpk_hi);  uint32_t* whi = (uint32_t*)p;
    cudaGetSymbolAddress(&p, g_wpk_lo);  uint32_t* wlo = (uint32_t*)p;
    cudaGetSymbolAddress(&p, g_apk_hi);  uint32_t* ahi = (uint32_t*)p;
    cudaGetSymbolAddress(&p, g_qloc);    float* qloc = (float*)p;
    cudaGetSymbolAddress(&p, g_kbuf);    float* kbuf = (float*)p;
    cudaGetSymbolAddress(&p, g_vbuf);    float* vbuf = (float*)p;

    cudaFuncSetAttribute(gemm_pk<0>, cudaFuncAttributeMaxDynamicSharedMemorySize, SMEM_MMA);
    cudaFuncSetAttribute(gemm_pk<1>, cudaFuncAttributeMaxDynamicSharedMemorySize, SMEM_MMA);

    const int WSZ = C_ * C2_;

    prep_w_kernel<<<4 * WSZ / 256, 256>>>(Wq, Wk, Wv, Wo, whi, wlo);
    {
        dim3 g(HW_ / 1024, C2_, B_);
        prep_x_kernel<<<g, 256>>>(x, xhi, mhi);
    }
    {
        dim3 g(HW_ / NTT, C_ / MT, B_);
        gemm_pk<0><<<g, 256, SMEM_MMA>>>(whi + 0 * WSZ, wlo + 0 * WSZ,
                                         nullptr, nullptr, mhi, qloc, nullptr);
    }
    {
        dim3 g(HW_ / NTT, C_ / MT, B_ * V_ * 2);
        gemm_pk<1><<<g, 256, SMEM_MMA>>>(whi + 1 * WSZ, wlo + 1 * WSZ,
                                         whi + 2 * WSZ, wlo + 2 * WSZ,
                                         xhi, kbuf, vbuf);
    }
    attn_kernel<<<B_ * NH_ * (HW_ / 256), 256>>>(qloc, kbuf, vbuf, ahi);
    {
        dim3 g(HW_ / NTT, C_ / MT, B_);
        gemm_pk<0><<<g, 256, SMEM_MMA>>>(whi + 3 * WSZ, wlo + 3 * WSZ,
                                         nullptr, nullptr, ahi, out, nullptr);
    }
}